// round 2
// baseline (speedup 1.0000x reference)
#include <cuda_runtime.h>
#include <math_constants.h>

#define NB  32
#define C   64
#define HW  1024
#define CHW 65536
#define EPS 1e-5f

// ---------------- scratch (device globals; no allocations allowed) ----------
__device__ float g_qn[NB * CHW];
__device__ float g_kn[NB * CHW];
__device__ float g_vn[NB * CHW];
__device__ float g_q [NB * CHW];
__device__ float g_k [NB * CHW];
__device__ float g_v [NB * CHW];
__device__ float g_attn[(size_t)NB * HW * HW];

// ---------------- 1. LayerNorm over full (C,H,W) per sample ----------------
// grid = NB*3 blocks, 256 threads. which = 0:q 1:k 2:v
__global__ __launch_bounds__(256) void ln_kernel(
    const float* __restrict__ q, const float* __restrict__ k, const float* __restrict__ v,
    const float* __restrict__ w1, const float* __restrict__ b1,
    const float* __restrict__ w2, const float* __restrict__ b2,
    const float* __restrict__ w3, const float* __restrict__ b3)
{
    int which = blockIdx.x % 3;
    int n     = blockIdx.x / 3;
    const float *x, *w, *b;
    float* dst;
    if (which == 0)      { x = q + n * CHW; w = w1; b = b1; dst = g_qn + n * CHW; }
    else if (which == 1) { x = k + n * CHW; w = w2; b = b2; dst = g_kn + n * CHW; }
    else                 { x = v + n * CHW; w = w3; b = b3; dst = g_vn + n * CHW; }

    int tid = threadIdx.x;
    float s = 0.f, ss = 0.f;
    for (int i = tid * 4; i < CHW; i += 256 * 4) {
        float4 val = *(const float4*)(x + i);
        s  += val.x + val.y + val.z + val.w;
        ss += val.x * val.x + val.y * val.y + val.z * val.z + val.w * val.w;
    }
    __shared__ float sm[256], sm2[256];
    sm[tid] = s; sm2[tid] = ss;
    __syncthreads();
    for (int o = 128; o > 0; o >>= 1) {
        if (tid < o) { sm[tid] += sm[tid + o]; sm2[tid] += sm2[tid + o]; }
        __syncthreads();
    }
    float mean = sm[0] * (1.0f / CHW);
    float var  = sm2[0] * (1.0f / CHW) - mean * mean;
    float rstd = rsqrtf(var + EPS);

    for (int i = tid * 4; i < CHW; i += 256 * 4) {
        float4 val = *(const float4*)(x + i);
        float4 wv  = *(const float4*)(w + i);
        float4 bv  = *(const float4*)(b + i);
        float4 o4;
        o4.x = (val.x - mean) * rstd * wv.x + bv.x;
        o4.y = (val.y - mean) * rstd * wv.y + bv.y;
        o4.z = (val.z - mean) * rstd * wv.z + bv.z;
        o4.w = (val.w - mean) * rstd * wv.w + bv.w;
        *(float4*)(dst + i) = o4;
    }
}

// ---------------- 2. 1x1-conv projection: Y[o,p] = sum_c W[o,c] X[c,p] + B[o]
// grid = (HW/128, NB, 3), block = 128
__global__ __launch_bounds__(128) void proj_kernel(
    const float* __restrict__ wq, const float* __restrict__ bq,
    const float* __restrict__ wk, const float* __restrict__ bk,
    const float* __restrict__ wv, const float* __restrict__ bv)
{
    int which = blockIdx.z;
    int n     = blockIdx.y;
    int p0    = blockIdx.x * 128;
    const float *src, *W, *B;
    float* dst;
    if (which == 0)      { src = g_qn; W = wq; B = bq; dst = g_q; }
    else if (which == 1) { src = g_kn; W = wk; B = bk; dst = g_k; }
    else                 { src = g_vn; W = wv; B = bv; dst = g_v; }

    __shared__ float Ws[C * C];          // 16 KB
    __shared__ float Xs[C * 128];        // 32 KB
    int tid = threadIdx.x;
    for (int i = tid; i < C * C; i += 128) Ws[i] = W[i];
    for (int c = 0; c < C; c++)
        Xs[c * 128 + tid] = src[n * CHW + c * HW + p0 + tid];
    __syncthreads();

    float xr[C];
#pragma unroll
    for (int c = 0; c < C; c++) xr[c] = Xs[c * 128 + tid];

    for (int o = 0; o < C; o++) {
        float acc = B[o];
#pragma unroll
        for (int c = 0; c < C; c++) acc += Ws[o * C + c] * xr[c];
        dst[n * CHW + o * HW + p0 + tid] = acc;
    }
}

// ---------------- 3. attn[i,j] = (1/8) sum_c k[c,i] q[c,j] --------------
// grid = (16, 16, NB), block = 256, 4x4 microtile
__global__ __launch_bounds__(256) void attn_kernel()
{
    int n  = blockIdx.z;
    int i0 = blockIdx.y * 64;
    int j0 = blockIdx.x * 64;

    __shared__ float Ks[C][64];   // [c][i]
    __shared__ float Qs[C][64];   // [c][j]
    int tid = threadIdx.x;
    for (int idx = tid; idx < C * 64; idx += 256) {
        int c = idx >> 6, x = idx & 63;
        Ks[c][x] = g_k[n * CHW + c * HW + i0 + x];
        Qs[c][x] = g_q[n * CHW + c * HW + j0 + x];
    }
    __syncthreads();

    int tx = tid % 16, ty = tid / 16;
    float acc[4][4] = {};
#pragma unroll 8
    for (int c = 0; c < C; c++) {
        float4 a = *(const float4*)&Ks[c][ty * 4];
        float4 b = *(const float4*)&Qs[c][tx * 4];
        float av[4] = {a.x, a.y, a.z, a.w};
        float bv[4] = {b.x, b.y, b.z, b.w};
#pragma unroll
        for (int ii = 0; ii < 4; ii++)
#pragma unroll
            for (int jj = 0; jj < 4; jj++)
                acc[ii][jj] += av[ii] * bv[jj];
    }
    size_t base = (size_t)n * HW * HW;
#pragma unroll
    for (int ii = 0; ii < 4; ii++) {
        int i = i0 + ty * 4 + ii;
#pragma unroll
        for (int jj = 0; jj < 4; jj++) {
            int j = j0 + tx * 4 + jj;
            g_attn[base + (size_t)i * HW + j] = acc[ii][jj] * 0.125f;
        }
    }
}

// ---------------- 4. softmax over i (per n, per column j) -------------------
// grid = (HW/32, NB), block = (32,32)
__global__ __launch_bounds__(1024) void softmax_kernel(float* __restrict__ attn_out)
{
    int n  = blockIdx.y;
    int j0 = blockIdx.x * 32;
    int tx = threadIdx.x, ty = threadIdx.y;
    float* base = g_attn + (size_t)n * HW * HW;
    int j = j0 + tx;

    float m = -CUDART_INF_F;
    for (int i = ty; i < HW; i += 32)
        m = fmaxf(m, base[(size_t)i * HW + j]);

    __shared__ float red[32][33];
    red[ty][tx] = m;
    __syncthreads();
    for (int o = 16; o > 0; o >>= 1) {
        if (ty < o) red[ty][tx] = fmaxf(red[ty][tx], red[ty + o][tx]);
        __syncthreads();
    }
    m = red[0][tx];
    __syncthreads();

    float s = 0.f;
    for (int i = ty; i < HW; i += 32)
        s += __expf(base[(size_t)i * HW + j] - m);
    red[ty][tx] = s;
    __syncthreads();
    for (int o = 16; o > 0; o >>= 1) {
        if (ty < o) red[ty][tx] += red[ty + o][tx];
        __syncthreads();
    }
    float rs = 1.0f / red[0][tx];

    for (int i = ty; i < HW; i += 32) {
        float vv = __expf(base[(size_t)i * HW + j] - m) * rs;
        base[(size_t)i * HW + j] = vv;
        if (attn_out)
            attn_out[(size_t)n * HW * HW + (size_t)i * HW + j] = vv;
    }
}

// ---------------- 5. out[c,j] = sum_i v[c,i] attn[i,j]; x = qn + out --------
// grid = (HW/64, NB), block = 256, 4x4 microtile, K staged by 64
__global__ __launch_bounds__(256) void out_kernel(float* __restrict__ xout)
{
    int n  = blockIdx.y;
    int j0 = blockIdx.x * 64;

    __shared__ float Vs[C][65];   // [c][i] (+pad)
    __shared__ float As[64][64];  // [i][j]
    int tid = threadIdx.x;
    int tx = tid % 16, ty = tid / 16;

    const float* vptr = g_v + n * CHW;
    const float* aptr = g_attn + (size_t)n * HW * HW;

    float acc[4][4] = {};
    for (int i0 = 0; i0 < HW; i0 += 64) {
        for (int idx = tid; idx < C * 64; idx += 256) {
            int r = idx >> 6, x = idx & 63;
            Vs[r][x] = vptr[r * HW + i0 + x];
            As[r][x] = aptr[(size_t)(i0 + r) * HW + j0 + x];
        }
        __syncthreads();
#pragma unroll 8
        for (int i = 0; i < 64; i++) {
            float av[4];
#pragma unroll
            for (int cc = 0; cc < 4; cc++) av[cc] = Vs[ty * 4 + cc][i];
            float4 b = *(const float4*)&As[i][tx * 4];
            float bv[4] = {b.x, b.y, b.z, b.w};
#pragma unroll
            for (int cc = 0; cc < 4; cc++)
#pragma unroll
                for (int jj = 0; jj < 4; jj++)
                    acc[cc][jj] += av[cc] * bv[jj];
        }
        __syncthreads();
    }

#pragma unroll
    for (int cc = 0; cc < 4; cc++) {
        int c = ty * 4 + cc;
#pragma unroll
        for (int jj = 0; jj < 4; jj++) {
            int j = j0 + tx * 4 + jj;
            xout[n * CHW + c * HW + j] = acc[cc][jj] + g_qn[n * CHW + c * HW + j];
        }
    }
}

// ---------------------------------------------------------------------------
extern "C" void kernel_launch(void* const* d_in, const int* in_sizes, int n_in,
                              void* d_out, int out_size)
{
    const float* query = (const float*)d_in[0];
    const float* key   = (const float*)d_in[1];
    const float* value = (const float*)d_in[2];
    const float* ln1w  = (const float*)d_in[3];
    const float* ln1b  = (const float*)d_in[4];
    const float* ln2w  = (const float*)d_in[5];
    const float* ln2b  = (const float*)d_in[6];
    const float* ln3w  = (const float*)d_in[7];
    const float* ln3b  = (const float*)d_in[8];
    const float* wq    = (const float*)d_in[9];
    const float* bq    = (const float*)d_in[10];
    const float* wk    = (const float*)d_in[11];
    const float* bk    = (const float*)d_in[12];
    const float* wv    = (const float*)d_in[13];
    const float* bv    = (const float*)d_in[14];

    float* out = (float*)d_out;
    const size_t XSZ = (size_t)NB * CHW;        // 2,097,152
    const size_t ASZ = (size_t)NB * HW * HW;    // 33,554,432

    float* x_out    = nullptr;
    float* attn_out = nullptr;
    size_t osz = (size_t)out_size;
    if (osz >= XSZ + ASZ)      { x_out = out; attn_out = out + XSZ; }
    else if (osz == ASZ)       { attn_out = out; }
    else                       { x_out = out; }

    ln_kernel<<<NB * 3, 256>>>(query, key, value, ln1w, ln1b, ln2w, ln2b, ln3w, ln3b);
    proj_kernel<<<dim3(HW / 128, NB, 3), 128>>>(wq, bq, wk, bk, wv, bv);
    attn_kernel<<<dim3(16, 16, NB), 256>>>();
    softmax_kernel<<<dim3(HW / 32, NB), dim3(32, 32)>>>(attn_out);
    if (x_out)
        out_kernel<<<dim3(HW / 64, NB), 256>>>(x_out);
}